// round 13
// baseline (speedup 1.0000x reference)
#include <cuda_runtime.h>
#include <stdint.h>
#include <math.h>

#define BB 64
#define SS 512
#define HH 1024
#define II 1024
#define CC 64
#define NCH (SS/CC)
#define NPAIR 36
#define LRI (0.01f/1024.0f)
#define EPSF 1e-5f

// ---------------- device state (no allocation allowed) ----------------
__device__ float g_bst[BB*II];
__device__ float g_tgt[(size_t)BB*SS*II];     // x@Wt + bt
__device__ float g_xg[(size_t)BB*SS*HH];      // x@Wg1 + bg + bo@Wg2
__device__ float g_base0[(size_t)BB*SS*II];   // x@W_init
__device__ float g_errAll[(size_t)BB*SS*II];  // full err history
__device__ float g_base[BB*CC*II];            // base0 - LRI*cross (per chunk)
__device__ float g_act[BB*CC*II];             // silu(inner)
__device__ float g_ttt[BB*CC*HH];
__device__ float g_gate[BB*CC*HH];
__device__ float g_Gx[(size_t)BB*NPAIR*CC*CC]; // Gram blocks, triangular (c,p)
__device__ float g_Wog[HH*HH];                // Wo @ Wg2
__device__ float g_bgog[HH];                  // bg + bo@Wg2

// ------------------------- helpers -------------------------
__device__ __forceinline__ void cpa16(uint32_t s, const void* g) {
    asm volatile("cp.async.cg.shared.global [%0], [%1], 16;" :: "r"(s), "l"(g));
}
__device__ __forceinline__ void ffma2(unsigned long long& c, unsigned long long a,
                                      unsigned long long b) {
    asm("fma.rn.f32x2 %0, %1, %2, %0;" : "+l"(c) : "l"(a), "l"(b));
}
__device__ __forceinline__ unsigned long long pk2(float lo, float hi) {
    unsigned long long r;
    asm("mov.b64 %0, {%1, %2};" : "=l"(r) : "f"(lo), "f"(hi));
    return r;
}
__device__ __forceinline__ void upk2(float& lo, float& hi, unsigned long long v) {
    asm("mov.b64 {%0, %1}, %2;" : "=f"(lo), "=f"(hi) : "l"(v));
}

// ---------------------------------------------------------------------
__global__ void k_initb(const float* __restrict__ bi) {
    int i = blockIdx.x * 1024 + threadIdx.x;     // grid 64 x 1024
    g_bst[i] = bi[i & 1023];
}

// g_bgog[n] = bg[n] + sum_j bo[j]*Wg2[j,n]
__global__ void k_bgog(const float* __restrict__ bo, const float* __restrict__ bg,
                       const float* __restrict__ Wg2) {
    int n = blockIdx.x * 256 + threadIdx.x;
    float s = bg[n];
    for (int j = 0; j < 1024; ++j) s += bo[j] * Wg2[(size_t)j*1024 + n];
    g_bgog[n] = s;
}

// ---------------------------------------------------------------------
// FFMA2 fp32 GEMM: 128x128 tile, 256 thr, K-slab 32, 3-stage cp.async.
// op 0: C=g_tgt   (A=x,  B=Wt,     +bias bt)
// op 1: C=g_xg    (A=x,  B=Wg1,    +bias bgog)
// op 2: chunk fused, grid(16,32): nb<8 -> g_ttt (B=Wo,+bo);
//       nb>=8 -> g_gate (B=g_Wog, +xg row for t0)
// op 4: C=g_Wog   (A=Wo, B=Wg2,    no bias)
// op 5: C=g_base0 (A=x,  B=W_init, no bias)
// ---------------------------------------------------------------------
#define GASTG 18432
#define GBSTG 16896
#define GSTG  (GASTG + GBSTG)
#define GSMEM (3*GSTG)

__global__ void __launch_bounds__(256, 2)
k_gemm2(int op, const float* __restrict__ Aex, const float* __restrict__ Bex,
        const float* __restrict__ bias, int t0) {
    const float *Ap, *Bp;
    float* Cp;
    const float* xgp = 0;
    int n0 = blockIdx.x * 128;
    const int m0 = blockIdx.y * 128;
    if (op == 0)      { Ap = Aex;   Bp = Bex; Cp = g_tgt; }
    else if (op == 1) { Ap = Aex;   Bp = Bex; Cp = g_xg; }
    else if (op == 2) {
        Ap = g_act;
        if (n0 < 1024) { Bp = Bex;   Cp = g_ttt; }
        else           { Bp = g_Wog; Cp = g_gate; n0 -= 1024; xgp = g_xg; }
    }
    else if (op == 4) { Ap = Aex;   Bp = Bex; Cp = g_Wog; }
    else              { Ap = Aex;   Bp = Bex; Cp = g_base0; }

    extern __shared__ __align__(16) char smg[];
    const uint32_t smb = (uint32_t)__cvta_generic_to_shared(smg);
    const int tid = threadIdx.x;
    const int tx = tid & 15, ty = tid >> 4;

    unsigned long long acc2[8][4];
    #pragma unroll
    for (int i = 0; i < 8; ++i)
        #pragma unroll
        for (int j = 0; j < 4; ++j) acc2[i][j] = 0ULL;

    uint32_t adst[4], bdst[4];
    const float *asrc[4], *bsrc[4];
    #pragma unroll
    for (int j = 0; j < 4; ++j) {
        int ac = tid + j*256;
        int ar = ac >> 3, aq = ac & 7;
        adst[j] = (uint32_t)(ar*144 + aq*16);
        asrc[j] = Ap + (size_t)(m0 + ar)*1024 + aq*4;
        int bc = tid + j*256;
        int br = bc >> 5, bq = bc & 31;
        bdst[j] = (uint32_t)(GASTG + br*528 + bq*16);
        bsrc[j] = Bp + (size_t)br*1024 + n0 + bq*4;
    }

    {   // prologue: slabs 0,1
        #pragma unroll
        for (int j = 0; j < 4; ++j) cpa16(smb + adst[j], asrc[j]);
        #pragma unroll
        for (int j = 0; j < 4; ++j) cpa16(smb + bdst[j], bsrc[j]);
        asm volatile("cp.async.commit_group;");
        const uint32_t s1 = smb + GSTG;
        #pragma unroll
        for (int j = 0; j < 4; ++j) cpa16(s1 + adst[j], asrc[j] + 32);
        #pragma unroll
        for (int j = 0; j < 4; ++j) cpa16(s1 + bdst[j], bsrc[j] + (size_t)32*1024);
        asm volatile("cp.async.commit_group;");
    }

    int stage = 0;
    for (int it = 0; it < 32; ++it) {
        asm volatile("cp.async.wait_group 1;");
        __syncthreads();
        if (it + 2 < 32) {
            const int k0 = (it + 2) * 32;
            const int ns = (stage + 2 >= 3) ? stage - 1 : stage + 2;
            const uint32_t s = smb + ns * GSTG;
            #pragma unroll
            for (int j = 0; j < 4; ++j) cpa16(s + adst[j], asrc[j] + k0);
            #pragma unroll
            for (int j = 0; j < 4; ++j) cpa16(s + bdst[j], bsrc[j] + (size_t)k0*1024);
            asm volatile("cp.async.commit_group;");
        } else {
            asm volatile("cp.async.commit_group;");
        }
        const uint32_t sA = smb + stage * GSTG;
        const uint32_t sB = sA + GASTG;
        #pragma unroll
        for (int k2 = 0; k2 < 32; k2 += 2) {
            float a0[8], a1[8];
            #pragma unroll
            for (int i = 0; i < 8; ++i) {
                float vx, vy;
                asm("ld.shared.v2.f32 {%0,%1},[%2];" : "=f"(vx), "=f"(vy)
                    : "r"(sA + (uint32_t)((ty*8 + i)*144 + k2*4)));
                a0[i] = vx; a1[i] = vy;
            }
            float b0x,b0y,b0z,b0w, b1x,b1y,b1z,b1w;
            float c0x,c0y,c0z,c0w, c1x,c1y,c1z,c1w;
            asm("ld.shared.v4.f32 {%0,%1,%2,%3},[%4];"
                : "=f"(b0x),"=f"(b0y),"=f"(b0z),"=f"(b0w)
                : "r"(sB + (uint32_t)(k2*528 + tx*16)));
            asm("ld.shared.v4.f32 {%0,%1,%2,%3},[%4];"
                : "=f"(b1x),"=f"(b1y),"=f"(b1z),"=f"(b1w)
                : "r"(sB + (uint32_t)(k2*528 + 256 + tx*16)));
            asm("ld.shared.v4.f32 {%0,%1,%2,%3},[%4];"
                : "=f"(c0x),"=f"(c0y),"=f"(c0z),"=f"(c0w)
                : "r"(sB + (uint32_t)((k2+1)*528 + tx*16)));
            asm("ld.shared.v4.f32 {%0,%1,%2,%3},[%4];"
                : "=f"(c1x),"=f"(c1y),"=f"(c1z),"=f"(c1w)
                : "r"(sB + (uint32_t)((k2+1)*528 + 256 + tx*16)));
            unsigned long long bb0 = pk2(b0x,b0y), bb1 = pk2(b0z,b0w);
            unsigned long long bb2 = pk2(b1x,b1y), bb3 = pk2(b1z,b1w);
            unsigned long long cb0 = pk2(c0x,c0y), cb1 = pk2(c0z,c0w);
            unsigned long long cb2 = pk2(c1x,c1y), cb3 = pk2(c1z,c1w);
            #pragma unroll
            for (int i = 0; i < 8; ++i) {
                unsigned long long a2 = pk2(a0[i], a0[i]);
                ffma2(acc2[i][0], a2, bb0);
                ffma2(acc2[i][1], a2, bb1);
                ffma2(acc2[i][2], a2, bb2);
                ffma2(acc2[i][3], a2, bb3);
                unsigned long long a3 = pk2(a1[i], a1[i]);
                ffma2(acc2[i][0], a3, cb0);
                ffma2(acc2[i][1], a3, cb1);
                ffma2(acc2[i][2], a3, cb2);
                ffma2(acc2[i][3], a3, cb3);
            }
        }
        stage = (stage + 1 >= 3) ? 0 : stage + 1;
    }

    const int cc0 = n0 + tx*4;
    #pragma unroll
    for (int i = 0; i < 8; ++i) {
        const int r = m0 + ty*8 + i;
        float v[8];
        upk2(v[0], v[1], acc2[i][0]);
        upk2(v[2], v[3], acc2[i][1]);
        upk2(v[4], v[5], acc2[i][2]);
        upk2(v[6], v[7], acc2[i][3]);
        if (xgp) {
            const size_t gr = ((size_t)(r >> 6)*SS + t0 + (r & 63))*1024;
            float4 x0 = *(const float4*)&xgp[gr + cc0];
            float4 x1 = *(const float4*)&xgp[gr + cc0 + 64];
            v[0]+=x0.x; v[1]+=x0.y; v[2]+=x0.z; v[3]+=x0.w;
            v[4]+=x1.x; v[5]+=x1.y; v[6]+=x1.z; v[7]+=x1.w;
        } else if (bias) {
            float4 b0 = *(const float4*)&bias[cc0];
            float4 b1 = *(const float4*)&bias[cc0 + 64];
            v[0]+=b0.x; v[1]+=b0.y; v[2]+=b0.z; v[3]+=b0.w;
            v[4]+=b1.x; v[5]+=b1.y; v[6]+=b1.z; v[7]+=b1.w;
        }
        float* d = &Cp[(size_t)r*1024 + cc0];
        *(float4*)(d)      = make_float4(v[0],v[1],v[2],v[3]);
        *(float4*)(d + 64) = make_float4(v[4],v[5],v[6],v[7]);
    }
}

// ---------------------------------------------------------------------
// All Gram blocks in one launch. grid (NPAIR, BB); pair -> (c,p), p<=c.
// Gx[b][tri(c)+p][t][s] = x_{c*64+t} . x_{p*64+s}
// ---------------------------------------------------------------------
__global__ void k_xxt_all(const float* __restrict__ x) {
    const int pair = blockIdx.x, b = blockIdx.y, tid = threadIdx.x;
    int c = 0, base = 0;
    while (base + c + 1 <= pair) { base += c + 1; c++; }
    const int p = pair - base;
    const int t0 = c * CC;
    const int tq = tid >> 4, tr = tid & 15;
    __shared__ float As[64][33];
    __shared__ float Bs[64][33];
    float acc[4][4];
    #pragma unroll
    for (int i = 0; i < 4; ++i)
        #pragma unroll
        for (int j = 0; j < 4; ++j) acc[i][j] = 0.f;
    for (int h0 = 0; h0 < HH; h0 += 32) {
        int r = tid >> 2, cq = (tid & 3) * 8;
        const float* xa = &x[((size_t)b*SS + t0 + r)*HH + h0 + cq];
        const float* xb = &x[((size_t)b*SS + p*CC + r)*HH + h0 + cq];
        float4 a0 = *(const float4*)xa, a1 = *(const float4*)(xa + 4);
        float4 b0 = *(const float4*)xb, b1 = *(const float4*)(xb + 4);
        As[r][cq+0]=a0.x; As[r][cq+1]=a0.y; As[r][cq+2]=a0.z; As[r][cq+3]=a0.w;
        As[r][cq+4]=a1.x; As[r][cq+5]=a1.y; As[r][cq+6]=a1.z; As[r][cq+7]=a1.w;
        Bs[r][cq+0]=b0.x; Bs[r][cq+1]=b0.y; Bs[r][cq+2]=b0.z; Bs[r][cq+3]=b0.w;
        Bs[r][cq+4]=b1.x; Bs[r][cq+5]=b1.y; Bs[r][cq+6]=b1.z; Bs[r][cq+7]=b1.w;
        __syncthreads();
        #pragma unroll 8
        for (int h = 0; h < 32; ++h) {
            float a0v=As[tq*4+0][h], a1v=As[tq*4+1][h];
            float a2v=As[tq*4+2][h], a3v=As[tq*4+3][h];
            float b0v=Bs[tr*4+0][h], b1v=Bs[tr*4+1][h];
            float b2v=Bs[tr*4+2][h], b3v=Bs[tr*4+3][h];
            acc[0][0]+=a0v*b0v; acc[0][1]+=a0v*b1v; acc[0][2]+=a0v*b2v; acc[0][3]+=a0v*b3v;
            acc[1][0]+=a1v*b0v; acc[1][1]+=a1v*b1v; acc[1][2]+=a1v*b2v; acc[1][3]+=a1v*b3v;
            acc[2][0]+=a2v*b0v; acc[2][1]+=a2v*b1v; acc[2][2]+=a2v*b2v; acc[2][3]+=a2v*b3v;
            acc[3][0]+=a3v*b0v; acc[3][1]+=a3v*b1v; acc[3][2]+=a3v*b2v; acc[3][3]+=a3v*b3v;
        }
        __syncthreads();
    }
    float* g = &g_Gx[((size_t)b*NPAIR + pair)*CC*CC];
    #pragma unroll
    for (int i = 0; i < 4; ++i)
        #pragma unroll
        for (int j = 0; j < 4; ++j)
            g[(tq*4+i)*CC + tr*4+j] = acc[i][j];
}

// ---------------------------------------------------------------------
// Cross-chunk correction: g_base = base0_chunk - LRI * sum_{p<c} Gx[c,p] @ Ep.
// grid (8, B), 256 thr.
// ---------------------------------------------------------------------
#define XSMEM 49152   // Gs 16KB + Es 32KB

__global__ void __launch_bounds__(256)
k_cross(int c, int t0) {
    extern __shared__ float xsm[];
    float* Gsm = xsm;          // [64 t][64 s]
    float* Esm = xsm + 4096;   // [64 s][128 i]
    const int b = blockIdx.y, ib = blockIdx.x * 128;
    const int tid = threadIdx.x, lane = tid & 31, wq = tid >> 5;
    const int tri = c * (c + 1) / 2;

    unsigned long long acc2[8][2];
    #pragma unroll
    for (int r = 0; r < 8; ++r) { acc2[r][0] = 0ULL; acc2[r][1] = 0ULL; }

    for (int p = 0; p < c; ++p) {
        __syncthreads();
        const float4* gsrc = (const float4*)&g_Gx[((size_t)b*NPAIR + tri + p)*CC*CC];
        #pragma unroll
        for (int l = 0; l < 4; ++l)
            ((float4*)Gsm)[tid + l*256] = gsrc[tid + l*256];
        #pragma unroll
        for (int l = 0; l < 8; ++l) {
            int f4 = tid + l*256;
            int s = f4 >> 5, q = f4 & 31;
            ((float4*)Esm)[s*32 + q] =
                *(const float4*)&g_errAll[((size_t)b*SS + p*CC + s)*II + ib + q*4];
        }
        __syncthreads();
        #pragma unroll 4
        for (int s = 0; s < 64; ++s) {
            float4 ev = ((float4*)Esm)[s*32 + lane];
            unsigned long long e0 = pk2(ev.x, ev.y), e1 = pk2(ev.z, ev.w);
            #pragma unroll
            for (int r = 0; r < 8; ++r) {
                float g = Gsm[(wq*8 + r)*64 + s];
                unsigned long long g2 = pk2(g, g);
                ffma2(acc2[r][0], g2, e0);
                ffma2(acc2[r][1], g2, e1);
            }
        }
    }
    #pragma unroll
    for (int r = 0; r < 8; ++r) {
        const int t = wq*8 + r;
        float v0, v1, v2, v3;
        upk2(v0, v1, acc2[r][0]);
        upk2(v2, v3, acc2[r][1]);
        float4 bb = *(const float4*)&g_base0[((size_t)b*SS + t0 + t)*II + ib + lane*4];
        *(float4*)&g_base[((b<<6) + t)*II + ib + lane*4] =
            make_float4(bb.x - LRI*v0, bb.y - LRI*v1, bb.z - LRI*v2, bb.w - LRI*v3);
    }
}

// ---------------------------------------------------------------------
// Intra-chunk recurrence. Reads corrected base + diagonal Gram block.
// ---------------------------------------------------------------------
__global__ void k_recur(int c, int t0) {
    __shared__ float Gs[CC*CC];
    const int b = blockIdx.y;
    const int i = blockIdx.x * 256 + threadIdx.x;
    const int tid = threadIdx.x;
    const float* gsrc = &g_Gx[((size_t)b*NPAIR + c*(c+1)/2 + c)*CC*CC];
    #pragma unroll
    for (int l = 0; l < 16; ++l)
        Gs[tid + l*256] = LRI * (gsrc[tid + l*256] + 1.0f);
    __syncthreads();

    float bstv = g_bst[b*II + i];
    float eh[CC];
    float sumerr = 0.f;
    #pragma unroll
    for (int t = 0; t < CC; ++t) {
        float inner = g_base[((b<<6)+t)*II + i] + bstv;
        #pragma unroll
        for (int s = 0; s < t; ++s) inner -= Gs[t*CC + s] * eh[s];
        float tg = g_tgt[((size_t)b*SS + t0 + t)*II + i];
        float e = inner - tg;
        eh[t] = e; sumerr += e;
        g_errAll[((size_t)b*SS + t0 + t)*II + i] = e;
        g_act[((b<<6)+t)*II + i] = inner / (1.0f + expf(-inner));
    }
    g_bst[b*II + i] = bstv - LRI * sumerr;
}

// ---------------------------------------------------------------------
__global__ void k_epi(const float* __restrict__ x, const float* __restrict__ gamma,
                      const float* __restrict__ beta, float* __restrict__ out, int t0) {
    const int row = blockIdx.x;
    const int b = row >> 6, t = row & 63;
    const int tid = threadIdx.x;
    const size_t xr = ((size_t)b*SS + t0 + t)*HH;
    float z[4], lsum = 0.f, lsq = 0.f;
    #pragma unroll
    for (int l = 0; l < 4; ++l) {
        int j = tid + l*256;
        float tv = g_ttt[(size_t)row*HH + j];
        float gv = g_gate[(size_t)row*HH + j];
        float gate = 1.0f / (1.0f + expf(-gv));
        float xv = x[xr + j];
        float zz = gate*tv + (1.0f - gate)*xv;
        z[l] = zz; lsum += zz; lsq += zz*zz;
    }
    __shared__ float s1[8], s2[8];
    #pragma unroll
    for (int off = 16; off > 0; off >>= 1) {
        lsum += __shfl_xor_sync(0xFFFFFFFFu, lsum, off);
        lsq  += __shfl_xor_sync(0xFFFFFFFFu, lsq,  off);
    }
    int lane = tid & 31, wid = tid >> 5;
    if (lane == 0) { s1[wid] = lsum; s2[wid] = lsq; }
    __syncthreads();
    if (wid == 0) {
        float v1 = (lane < 8) ? s1[lane] : 0.f;
        float v2 = (lane < 8) ? s2[lane] : 0.f;
        #pragma unroll
        for (int off = 4; off > 0; off >>= 1) {
            v1 += __shfl_xor_sync(0xFFFFFFFFu, v1, off);
            v2 += __shfl_xor_sync(0xFFFFFFFFu, v2, off);
        }
        if (lane == 0) { s1[0] = v1; s2[0] = v2; }
    }
    __syncthreads();
    float mu  = s1[0] * (1.0f / HH);
    float var = s2[0] * (1.0f / HH) - mu*mu;
    float inv = rsqrtf(var + EPSF);
    #pragma unroll
    for (int l = 0; l < 4; ++l) {
        int j = tid + l*256;
        out[xr + j] = (z[l] - mu) * inv * gamma[j] + beta[j];
    }
}

// ---------------------------------------------------------------------
extern "C" void kernel_launch(void* const* d_in, const int* in_sizes, int n_in,
                              void* d_out, int out_size) {
    const float* x      = (const float*)d_in[0];
    const float* W_init = (const float*)d_in[1];
    const float* b_init = (const float*)d_in[2];
    const float* Wt     = (const float*)d_in[3];
    const float* bt     = (const float*)d_in[4];
    const float* Wo     = (const float*)d_in[5];
    const float* bo     = (const float*)d_in[6];
    const float* Wg     = (const float*)d_in[7];
    const float* bg     = (const float*)d_in[8];
    const float* gamma  = (const float*)d_in[9];
    const float* beta   = (const float*)d_in[10];
    float* out = (float*)d_out;

    static int attr_done = 0;
    if (!attr_done) {
        cudaFuncSetAttribute(k_gemm2, cudaFuncAttributeMaxDynamicSharedMemorySize, GSMEM);
        cudaFuncSetAttribute(k_cross, cudaFuncAttributeMaxDynamicSharedMemorySize, XSMEM);
        attr_done = 1;
    }

    float* p_bgog;
    cudaGetSymbolAddress((void**)&p_bgog, g_bgog);

    k_initb<<<64, 1024>>>(b_init);                                   // 0
    k_gemm2<<<dim3(8,256), 256, GSMEM>>>(5, x, W_init, 0, 0);        // 1: base0
    k_gemm2<<<dim3(8,256), 256, GSMEM>>>(0, x, Wt, bt, 0);           // 2: tgt
    k_xxt_all<<<dim3(NPAIR, BB), 256>>>(x);                          // 3: all Gram
    k_gemm2<<<dim3(8,8),  256, GSMEM>>>(4, Wo, Wg + 1024*1024, 0, 0);// 4: Wog
    k_bgog<<<4, 256>>>(bo, bg, Wg + 1024*1024);                      // 5
    k_gemm2<<<dim3(8,256), 256, GSMEM>>>(1, x, Wg, p_bgog, 0);       // 6: xg

    for (int c = 0; c < NCH; ++c) {
        const int t0 = c * CC;
        k_cross<<<dim3(8, BB), 256, XSMEM>>>(c, t0);
        k_recur<<<dim3(4, BB), 256>>>(c, t0);
        k_gemm2<<<dim3(16,32), 256, GSMEM>>>(2, 0, Wo, bo, t0);
        k_epi<<<BB*CC, 256>>>(x, gamma, beta, out, t0);
    }
}

// round 14
// speedup vs baseline: 1.5625x; 1.5625x over previous
#include <cuda_runtime.h>
#include <stdint.h>
#include <math.h>

#define BB 64
#define SS 512
#define HH 1024
#define II 1024
#define CC 64
#define NCH (SS/CC)
#define LRI (0.01f/1024.0f)
#define EPSF 1e-5f

// ---------------- device state (no allocation allowed) ----------------
__device__ float g_bst[BB*II];
__device__ float g_tgt[(size_t)BB*SS*II];     // x@Wt + bt
__device__ float g_xg[(size_t)BB*SS*HH];      // x@Wg1 + bg + bo@Wg2
__device__ float g_base0[(size_t)BB*SS*II];   // x@W_init
__device__ float g_errAll[(size_t)BB*SS*II];  // full err history
__device__ float g_base[BB*CC*II];            // base0 - LRI*cross (chunks c>0)
__device__ float g_act[BB*CC*II];             // silu(inner)
__device__ float g_ttt[BB*CC*HH];
__device__ float g_gate[BB*CC*HH];
__device__ float g_Gx[(size_t)BB*NCH*CC*CC];  // Gram row for current chunk
__device__ float g_Wog[HH*HH];                // Wo @ Wg2
__device__ float g_bgog[HH];                  // bg + bo@Wg2

// ------------------------- helpers -------------------------
__device__ __forceinline__ void cpa16(uint32_t s, const void* g) {
    asm volatile("cp.async.cg.shared.global [%0], [%1], 16;" :: "r"(s), "l"(g));
}
__device__ __forceinline__ void ffma2(unsigned long long& c, unsigned long long a,
                                      unsigned long long b) {
    asm("fma.rn.f32x2 %0, %1, %2, %0;" : "+l"(c) : "l"(a), "l"(b));
}
__device__ __forceinline__ unsigned long long pk2(float lo, float hi) {
    unsigned long long r;
    asm("mov.b64 %0, {%1, %2};" : "=l"(r) : "f"(lo), "f"(hi));
    return r;
}
__device__ __forceinline__ void upk2(float& lo, float& hi, unsigned long long v) {
    asm("mov.b64 {%0, %1}, %2;" : "=f"(lo), "=f"(hi) : "l"(v));
}

// ---------------------------------------------------------------------
__global__ void k_initb(const float* __restrict__ bi) {
    int i = blockIdx.x * 1024 + threadIdx.x;     // grid 64 x 1024
    g_bst[i] = bi[i & 1023];
}

// g_bgog[n] = bg[n] + sum_j bo[j]*Wg2[j,n]
__global__ void k_bgog(const float* __restrict__ bo, const float* __restrict__ bg,
                       const float* __restrict__ Wg2) {
    int n = blockIdx.x * 256 + threadIdx.x;
    float s = bg[n];
    for (int j = 0; j < 1024; ++j) s += bo[j] * Wg2[(size_t)j*1024 + n];
    g_bgog[n] = s;
}

// ---------------------------------------------------------------------
// FFMA2 fp32 GEMM: 128x128 tile, 256 thr, K-slab 32, 3-stage cp.async.
// op 0: C=g_tgt   (A=x,  B=Wt,     +bias bt)
// op 1: C=g_xg    (A=x,  B=Wg1,    +bias bgog)
// op 2: chunk fused, grid(16,32): nb<8 -> g_ttt (B=Wo,+bo);
//       nb>=8 -> g_gate (B=g_Wog, +xg row for t0)
// op 4: C=g_Wog   (A=Wo, B=Wg2,    no bias)
// op 5: C=g_base0 (A=x,  B=W_init, no bias)
// ---------------------------------------------------------------------
#define GASTG 18432
#define GBSTG 16896
#define GSTG  (GASTG + GBSTG)
#define GSMEM (3*GSTG)

__global__ void __launch_bounds__(256, 2)
k_gemm2(int op, const float* __restrict__ Aex, const float* __restrict__ Bex,
        const float* __restrict__ bias, int t0) {
    const float *Ap, *Bp;
    float* Cp;
    const float* xgp = 0;
    int n0 = blockIdx.x * 128;
    const int m0 = blockIdx.y * 128;
    if (op == 0)      { Ap = Aex;   Bp = Bex; Cp = g_tgt; }
    else if (op == 1) { Ap = Aex;   Bp = Bex; Cp = g_xg; }
    else if (op == 2) {
        Ap = g_act;
        if (n0 < 1024) { Bp = Bex;   Cp = g_ttt; }
        else           { Bp = g_Wog; Cp = g_gate; n0 -= 1024; xgp = g_xg; }
    }
    else if (op == 4) { Ap = Aex;   Bp = Bex; Cp = g_Wog; }
    else              { Ap = Aex;   Bp = Bex; Cp = g_base0; }

    extern __shared__ __align__(16) char smg[];
    const uint32_t smb = (uint32_t)__cvta_generic_to_shared(smg);
    const int tid = threadIdx.x;
    const int tx = tid & 15, ty = tid >> 4;

    unsigned long long acc2[8][4];
    #pragma unroll
    for (int i = 0; i < 8; ++i)
        #pragma unroll
        for (int j = 0; j < 4; ++j) acc2[i][j] = 0ULL;

    uint32_t adst[4], bdst[4];
    const float *asrc[4], *bsrc[4];
    #pragma unroll
    for (int j = 0; j < 4; ++j) {
        int ac = tid + j*256;
        int ar = ac >> 3, aq = ac & 7;
        adst[j] = (uint32_t)(ar*144 + aq*16);
        asrc[j] = Ap + (size_t)(m0 + ar)*1024 + aq*4;
        int bc = tid + j*256;
        int br = bc >> 5, bq = bc & 31;
        bdst[j] = (uint32_t)(GASTG + br*528 + bq*16);
        bsrc[j] = Bp + (size_t)br*1024 + n0 + bq*4;
    }

    {   // prologue: slabs 0,1
        #pragma unroll
        for (int j = 0; j < 4; ++j) cpa16(smb + adst[j], asrc[j]);
        #pragma unroll
        for (int j = 0; j < 4; ++j) cpa16(smb + bdst[j], bsrc[j]);
        asm volatile("cp.async.commit_group;");
        const uint32_t s1 = smb + GSTG;
        #pragma unroll
        for (int j = 0; j < 4; ++j) cpa16(s1 + adst[j], asrc[j] + 32);
        #pragma unroll
        for (int j = 0; j < 4; ++j) cpa16(s1 + bdst[j], bsrc[j] + (size_t)32*1024);
        asm volatile("cp.async.commit_group;");
    }

    int stage = 0;
    for (int it = 0; it < 32; ++it) {
        asm volatile("cp.async.wait_group 1;");
        __syncthreads();
        if (it + 2 < 32) {
            const int k0 = (it + 2) * 32;
            const int ns = (stage + 2 >= 3) ? stage - 1 : stage + 2;
            const uint32_t s = smb + ns * GSTG;
            #pragma unroll
            for (int j = 0; j < 4; ++j) cpa16(s + adst[j], asrc[j] + k0);
            #pragma unroll
            for (int j = 0; j < 4; ++j) cpa16(s + bdst[j], bsrc[j] + (size_t)k0*1024);
            asm volatile("cp.async.commit_group;");
        } else {
            asm volatile("cp.async.commit_group;");
        }
        const uint32_t sA = smb + stage * GSTG;
        const uint32_t sB = sA + GASTG;
        #pragma unroll
        for (int k2 = 0; k2 < 32; k2 += 2) {
            float a0[8], a1[8];
            #pragma unroll
            for (int i = 0; i < 8; ++i) {
                float vx, vy;
                asm("ld.shared.v2.f32 {%0,%1},[%2];" : "=f"(vx), "=f"(vy)
                    : "r"(sA + (uint32_t)((ty*8 + i)*144 + k2*4)));
                a0[i] = vx; a1[i] = vy;
            }
            float b0x,b0y,b0z,b0w, b1x,b1y,b1z,b1w;
            float c0x,c0y,c0z,c0w, c1x,c1y,c1z,c1w;
            asm("ld.shared.v4.f32 {%0,%1,%2,%3},[%4];"
                : "=f"(b0x),"=f"(b0y),"=f"(b0z),"=f"(b0w)
                : "r"(sB + (uint32_t)(k2*528 + tx*16)));
            asm("ld.shared.v4.f32 {%0,%1,%2,%3},[%4];"
                : "=f"(b1x),"=f"(b1y),"=f"(b1z),"=f"(b1w)
                : "r"(sB + (uint32_t)(k2*528 + 256 + tx*16)));
            asm("ld.shared.v4.f32 {%0,%1,%2,%3},[%4];"
                : "=f"(c0x),"=f"(c0y),"=f"(c0z),"=f"(c0w)
                : "r"(sB + (uint32_t)((k2+1)*528 + tx*16)));
            asm("ld.shared.v4.f32 {%0,%1,%2,%3},[%4];"
                : "=f"(c1x),"=f"(c1y),"=f"(c1z),"=f"(c1w)
                : "r"(sB + (uint32_t)((k2+1)*528 + 256 + tx*16)));
            unsigned long long bb0 = pk2(b0x,b0y), bb1 = pk2(b0z,b0w);
            unsigned long long bb2 = pk2(b1x,b1y), bb3 = pk2(b1z,b1w);
            unsigned long long cb0 = pk2(c0x,c0y), cb1 = pk2(c0z,c0w);
            unsigned long long cb2 = pk2(c1x,c1y), cb3 = pk2(c1z,c1w);
            #pragma unroll
            for (int i = 0; i < 8; ++i) {
                unsigned long long a2 = pk2(a0[i], a0[i]);
                ffma2(acc2[i][0], a2, bb0);
                ffma2(acc2[i][1], a2, bb1);
                ffma2(acc2[i][2], a2, bb2);
                ffma2(acc2[i][3], a2, bb3);
                unsigned long long a3 = pk2(a1[i], a1[i]);
                ffma2(acc2[i][0], a3, cb0);
                ffma2(acc2[i][1], a3, cb1);
                ffma2(acc2[i][2], a3, cb2);
                ffma2(acc2[i][3], a3, cb3);
            }
        }
        stage = (stage + 1 >= 3) ? 0 : stage + 1;
    }

    const int cc0 = n0 + tx*4;
    #pragma unroll
    for (int i = 0; i < 8; ++i) {
        const int r = m0 + ty*8 + i;
        float v[8];
        upk2(v[0], v[1], acc2[i][0]);
        upk2(v[2], v[3], acc2[i][1]);
        upk2(v[4], v[5], acc2[i][2]);
        upk2(v[6], v[7], acc2[i][3]);
        if (xgp) {
            const size_t gr = ((size_t)(r >> 6)*SS + t0 + (r & 63))*1024;
            float4 x0 = *(const float4*)&xgp[gr + cc0];
            float4 x1 = *(const float4*)&xgp[gr + cc0 + 64];
            v[0]+=x0.x; v[1]+=x0.y; v[2]+=x0.z; v[3]+=x0.w;
            v[4]+=x1.x; v[5]+=x1.y; v[6]+=x1.z; v[7]+=x1.w;
        } else if (bias) {
            float4 b0 = *(const float4*)&bias[cc0];
            float4 b1 = *(const float4*)&bias[cc0 + 64];
            v[0]+=b0.x; v[1]+=b0.y; v[2]+=b0.z; v[3]+=b0.w;
            v[4]+=b1.x; v[5]+=b1.y; v[6]+=b1.z; v[7]+=b1.w;
        }
        float* d = &Cp[(size_t)r*1024 + cc0];
        *(float4*)(d)      = make_float4(v[0],v[1],v[2],v[3]);
        *(float4*)(d + 64) = make_float4(v[4],v[5],v[6],v[7]);
    }
}

// ---------------------------------------------------------------------
// Gram blocks for current chunk: Gx[b][p] = Xc @ Xp^T. grid (c+1, B).
// ---------------------------------------------------------------------
__global__ void k_xxt(const float* __restrict__ x, int t0) {
    const int p = blockIdx.x, b = blockIdx.y, tid = threadIdx.x;
    const int tq = tid >> 4, tr = tid & 15;
    __shared__ float As[64][33];
    __shared__ float Bs[64][33];
    float acc[4][4];
    #pragma unroll
    for (int i = 0; i < 4; ++i)
        #pragma unroll
        for (int j = 0; j < 4; ++j) acc[i][j] = 0.f;
    for (int h0 = 0; h0 < HH; h0 += 32) {
        int r = tid >> 2, cq = (tid & 3) * 8;
        const float* xa = &x[((size_t)b*SS + t0 + r)*HH + h0 + cq];
        const float* xb = &x[((size_t)b*SS + p*CC + r)*HH + h0 + cq];
        float4 a0 = *(const float4*)xa, a1 = *(const float4*)(xa + 4);
        float4 b0 = *(const float4*)xb, b1 = *(const float4*)(xb + 4);
        As[r][cq+0]=a0.x; As[r][cq+1]=a0.y; As[r][cq+2]=a0.z; As[r][cq+3]=a0.w;
        As[r][cq+4]=a1.x; As[r][cq+5]=a1.y; As[r][cq+6]=a1.z; As[r][cq+7]=a1.w;
        Bs[r][cq+0]=b0.x; Bs[r][cq+1]=b0.y; Bs[r][cq+2]=b0.z; Bs[r][cq+3]=b0.w;
        Bs[r][cq+4]=b1.x; Bs[r][cq+5]=b1.y; Bs[r][cq+6]=b1.z; Bs[r][cq+7]=b1.w;
        __syncthreads();
        #pragma unroll 8
        for (int h = 0; h < 32; ++h) {
            float a0v=As[tq*4+0][h], a1v=As[tq*4+1][h];
            float a2v=As[tq*4+2][h], a3v=As[tq*4+3][h];
            float b0v=Bs[tr*4+0][h], b1v=Bs[tr*4+1][h];
            float b2v=Bs[tr*4+2][h], b3v=Bs[tr*4+3][h];
            acc[0][0]+=a0v*b0v; acc[0][1]+=a0v*b1v; acc[0][2]+=a0v*b2v; acc[0][3]+=a0v*b3v;
            acc[1][0]+=a1v*b0v; acc[1][1]+=a1v*b1v; acc[1][2]+=a1v*b2v; acc[1][3]+=a1v*b3v;
            acc[2][0]+=a2v*b0v; acc[2][1]+=a2v*b1v; acc[2][2]+=a2v*b2v; acc[2][3]+=a2v*b3v;
            acc[3][0]+=a3v*b0v; acc[3][1]+=a3v*b1v; acc[3][2]+=a3v*b2v; acc[3][3]+=a3v*b3v;
        }
        __syncthreads();
    }
    float* g = &g_Gx[(((size_t)b*NCH + p)*CC)*CC];
    #pragma unroll
    for (int i = 0; i < 4; ++i)
        #pragma unroll
        for (int j = 0; j < 4; ++j)
            g[(tq*4+i)*CC + tr*4+j] = acc[i][j];
}

// ---------------------------------------------------------------------
// Cross-chunk correction (c >= 1): g_base = base0 - LRI * sum_{p<c} Gx[p]@Ep
// grid (8, B), 256 thr.
// ---------------------------------------------------------------------
#define XSMEM 49152   // Gs 16KB + Es 32KB

__global__ void __launch_bounds__(256)
k_cross(int c, int t0) {
    extern __shared__ float xsm[];
    float* Gsm = xsm;          // [64 t][64 s]
    float* Esm = xsm + 4096;   // [64 s][128 i]
    const int b = blockIdx.y, ib = blockIdx.x * 128;
    const int tid = threadIdx.x, lane = tid & 31, wq = tid >> 5;

    unsigned long long acc2[8][2];
    #pragma unroll
    for (int r = 0; r < 8; ++r) { acc2[r][0] = 0ULL; acc2[r][1] = 0ULL; }

    for (int p = 0; p < c; ++p) {
        __syncthreads();
        const float4* gsrc = (const float4*)&g_Gx[(((size_t)b*NCH + p)*CC)*CC];
        #pragma unroll
        for (int l = 0; l < 4; ++l)
            ((float4*)Gsm)[tid + l*256] = gsrc[tid + l*256];
        #pragma unroll
        for (int l = 0; l < 8; ++l) {
            int f4 = tid + l*256;
            int s = f4 >> 5, q = f4 & 31;
            ((float4*)Esm)[s*32 + q] =
                *(const float4*)&g_errAll[((size_t)b*SS + p*CC + s)*II + ib + q*4];
        }
        __syncthreads();
        #pragma unroll 4
        for (int s = 0; s < 64; ++s) {
            float4 ev = ((float4*)Esm)[s*32 + lane];
            unsigned long long e0 = pk2(ev.x, ev.y), e1 = pk2(ev.z, ev.w);
            #pragma unroll
            for (int r = 0; r < 8; ++r) {
                float g = Gsm[(wq*8 + r)*64 + s];
                unsigned long long g2 = pk2(g, g);
                ffma2(acc2[r][0], g2, e0);
                ffma2(acc2[r][1], g2, e1);
            }
        }
    }
    #pragma unroll
    for (int r = 0; r < 8; ++r) {
        const int t = wq*8 + r;
        float v0, v1, v2, v3;
        upk2(v0, v1, acc2[r][0]);
        upk2(v2, v3, acc2[r][1]);
        float4 bb = *(const float4*)&g_base0[((size_t)b*SS + t0 + t)*II + ib + lane*4];
        *(float4*)&g_base[((b<<6) + t)*II + ib + lane*4] =
            make_float4(bb.x - LRI*v0, bb.y - LRI*v1, bb.z - LRI*v2, bb.w - LRI*v3);
    }
}

// ---------------------------------------------------------------------
// Intra-chunk recurrence. c==0 reads g_base0 directly (no k_cross copy).
// ---------------------------------------------------------------------
__global__ void k_recur(int c, int t0) {
    __shared__ float Gs[CC*CC];
    const int b = blockIdx.y;
    const int i = blockIdx.x * 256 + threadIdx.x;
    const int tid = threadIdx.x;
    const float* gsrc = &g_Gx[(((size_t)b*NCH + c)*CC)*CC];
    #pragma unroll
    for (int l = 0; l < 16; ++l)
        Gs[tid + l*256] = LRI * (gsrc[tid + l*256] + 1.0f);
    __syncthreads();

    // base source: chunk scratch (c>0) or base0 rows directly (c==0)
    const float* bsrc;
    size_t brow;
    if (c == 0) { bsrc = &g_base0[((size_t)b*SS + t0)*II + i]; brow = II; }
    else        { bsrc = &g_base[((size_t)(b<<6))*II + i];     brow = II; }

    float bstv = g_bst[b*II + i];
    float eh[CC];
    float sumerr = 0.f;
    #pragma unroll
    for (int t = 0; t < CC; ++t) {
        float inner = bsrc[t*brow] + bstv;
        #pragma unroll
        for (int s = 0; s < t; ++s) inner -= Gs[t*CC + s] * eh[s];
        float tg = g_tgt[((size_t)b*SS + t0 + t)*II + i];
        float e = inner - tg;
        eh[t] = e; sumerr += e;
        g_errAll[((size_t)b*SS + t0 + t)*II + i] = e;
        g_act[((b<<6)+t)*II + i] = inner / (1.0f + expf(-inner));
    }
    g_bst[b*II + i] = bstv - LRI * sumerr;
}

// ---------------------------------------------------------------------
__global__ void k_epi(const float* __restrict__ x, const float* __restrict__ gamma,
                      const float* __restrict__ beta, float* __restrict__ out, int t0) {
    const int row = blockIdx.x;
    const int b = row >> 6, t = row & 63;
    const int tid = threadIdx.x;
    const size_t xr = ((size_t)b*SS + t0 + t)*HH;
    float z[4], lsum = 0.f, lsq = 0.f;
    #pragma unroll
    for (int l = 0; l < 4; ++l) {
        int j = tid + l*256;
        float tv = g_ttt[(size_t)row*HH + j];
        float gv = g_gate[(size_t)row*HH + j];
        float gate = 1.0f / (1.0f + expf(-gv));
        float xv = x[xr + j];
        float zz = gate*tv + (1.0f - gate)*xv;
        z[l] = zz; lsum += zz; lsq += zz*zz;
    }
    __shared__ float s1[8], s2[8];
    #pragma unroll
    for (int off = 16; off > 0; off >>= 1) {
        lsum += __shfl_xor_sync(0xFFFFFFFFu, lsum, off);
        lsq  += __shfl_xor_sync(0xFFFFFFFFu, lsq,  off);
    }
    int lane = tid & 31, wid = tid >> 5;
    if (lane == 0) { s1[wid] = lsum; s2[wid] = lsq; }
    __syncthreads();
    if (wid == 0) {
        float v1 = (lane < 8) ? s1[lane] : 0.f;
        float v2 = (lane < 8) ? s2[lane] : 0.f;
        #pragma unroll
        for (int off = 4; off > 0; off >>= 1) {
            v1 += __shfl_xor_sync(0xFFFFFFFFu, v1, off);
            v2 += __shfl_xor_sync(0xFFFFFFFFu, v2, off);
        }
        if (lane == 0) { s1[0] = v1; s2[0] = v2; }
    }
    __syncthreads();
    float mu  = s1[0] * (1.0f / HH);
    float var = s2[0] * (1.0f / HH) - mu*mu;
    float inv = rsqrtf(var + EPSF);
    #pragma unroll
    for (int l = 0; l < 4; ++l) {
        int j = tid + l*256;
        out[xr + j] = (z[l] - mu) * inv * gamma[j] + beta[j];
    }
}

// ---------------------------------------------------------------------
extern "C" void kernel_launch(void* const* d_in, const int* in_sizes, int n_in,
                              void* d_out, int out_size) {
    const float* x      = (const float*)d_in[0];
    const float* W_init = (const float*)d_in[1];
    const float* b_init = (const float*)d_in[2];
    const float* Wt     = (const float*)d_in[3];
    const float* bt     = (const float*)d_in[4];
    const float* Wo     = (const float*)d_in[5];
    const float* bo     = (const float*)d_in[6];
    const float* Wg     = (const float*)d_in[7];
    const float* bg     = (const float*)d_in[8];
    const float* gamma  = (const float*)d_in[9];
    const float* beta   = (const float*)d_in[10];
    float* out = (float*)d_out;

    static int attr_done = 0;
    if (!attr_done) {
        cudaFuncSetAttribute(k_gemm2, cudaFuncAttributeMaxDynamicSharedMemorySize, GSMEM);
        cudaFuncSetAttribute(k_cross, cudaFuncAttributeMaxDynamicSharedMemorySize, XSMEM);
        attr_done = 1;
    }

    float* p_bgog;
    cudaGetSymbolAddress((void**)&p_bgog, g_bgog);

    // chunk-0 front matter interleaved with setup GEMMs (round-12 structure)
    k_initb<<<64, 1024>>>(b_init);                                   // 0
    k_gemm2<<<dim3(8,256), 256, GSMEM>>>(5, x, W_init, 0, 0);        // 1: base0
    k_gemm2<<<dim3(8,256), 256, GSMEM>>>(0, x, Wt, bt, 0);           // 2: tgt
    k_xxt<<<dim3(1, BB), 256>>>(x, 0);                               // 3
    k_recur<<<dim3(4, BB), 256>>>(0, 0);                             // 4 (reads base0)
    k_gemm2<<<dim3(8,8),  256, GSMEM>>>(4, Wo, Wg + 1024*1024, 0, 0);// 5: Wog
    k_bgog<<<4, 256>>>(bo, bg, Wg + 1024*1024);                      // 6
    k_gemm2<<<dim3(8,256), 256, GSMEM>>>(1, x, Wg, p_bgog, 0);       // 7: xg
    k_gemm2<<<dim3(16,32), 256, GSMEM>>>(2, 0, Wo, bo, 0);           // 8: ttt+gate
    k_epi<<<BB*CC, 256>>>(x, gamma, beta, out, 0);                   // 9

    for (int c = 1; c < NCH; ++c) {
        const int t0 = c * CC;
        k_xxt<<<dim3(c + 1, BB), 256>>>(x, t0);
        k_cross<<<dim3(8, BB), 256, XSMEM>>>(c, t0);
        k_recur<<<dim3(4, BB), 256>>>(c, t0);
        k_gemm2<<<dim3(16,32), 256, GSMEM>>>(2, 0, Wo, bo, t0);
        k_epi<<<BB*CC, 256>>>(x, gamma, beta, out, t0);
    }
}

// round 15
// speedup vs baseline: 1.5678x; 1.0033x over previous
#include <cuda_runtime.h>
#include <stdint.h>
#include <math.h>

#define BB 64
#define SS 512
#define HH 1024
#define II 1024
#define CC 64
#define NCH (SS/CC)
#define LRI (0.01f/1024.0f)
#define EPSF 1e-5f

// ---------------- device state (no allocation allowed) ----------------
__device__ float g_bst[BB*II];
__device__ float g_tgt[(size_t)BB*SS*II];     // x@Wt + bt
__device__ float g_xg[(size_t)BB*SS*HH];      // x@Wg1 + bg + bo@Wg2
__device__ float g_base0[(size_t)BB*SS*II];   // x@W_init
__device__ float g_errAll[(size_t)BB*SS*II];  // full err history
__device__ float g_base[BB*CC*II];            // base0 - LRI*cross (chunks c>0)
__device__ float g_act[BB*CC*II];             // silu(inner)
__device__ float g_ttt[BB*CC*HH];
__device__ float g_gate[BB*CC*HH];
__device__ float g_Gx[(size_t)BB*NCH*CC*CC];  // Gram row for current chunk
__device__ float g_Wog[HH*HH];                // Wo @ Wg2
__device__ float g_bgog[HH];                  // bg + bo@Wg2

// ------------------------- helpers -------------------------
__device__ __forceinline__ void cpa16(uint32_t s, const void* g) {
    asm volatile("cp.async.cg.shared.global [%0], [%1], 16;" :: "r"(s), "l"(g));
}
__device__ __forceinline__ void ffma2(unsigned long long& c, unsigned long long a,
                                      unsigned long long b) {
    asm("fma.rn.f32x2 %0, %1, %2, %0;" : "+l"(c) : "l"(a), "l"(b));
}
__device__ __forceinline__ unsigned long long pk2(float lo, float hi) {
    unsigned long long r;
    asm("mov.b64 %0, {%1, %2};" : "=l"(r) : "f"(lo), "f"(hi));
    return r;
}
__device__ __forceinline__ void upk2(float& lo, float& hi, unsigned long long v) {
    asm("mov.b64 {%0, %1}, %2;" : "=f"(lo), "=f"(hi) : "l"(v));
}

// ---------------------------------------------------------------------
__global__ void k_initb(const float* __restrict__ bi) {
    int i = blockIdx.x * 1024 + threadIdx.x;     // grid 64 x 1024
    g_bst[i] = bi[i & 1023];
}

// g_bgog[n] = bg[n] + sum_j bo[j]*Wg2[j,n]
__global__ void k_bgog(const float* __restrict__ bo, const float* __restrict__ bg,
                       const float* __restrict__ Wg2) {
    int n = blockIdx.x * 256 + threadIdx.x;
    float s = bg[n];
    for (int j = 0; j < 1024; ++j) s += bo[j] * Wg2[(size_t)j*1024 + n];
    g_bgog[n] = s;
}

// ---------------------------------------------------------------------
// FFMA2 fp32 GEMM: 128x128 tile, 256 thr, K-slab 32, 3-stage cp.async.
// op 2: chunk fused, grid(16,32): nb<8 -> g_ttt (B=Bex=Wo, +bias bo);
//       nb>=8 -> g_gate (B=g_Wog, +xg row for t0)
// op 4: C=g_Wog (A=Aex=Wo, B=Bex=Wg2, no bias)
// op 7: merged big GEMMs, grid (8,256,3):
//       z=0: C=g_base0 (A=x, B=Bex2=W_init, no bias)
//       z=1: C=g_tgt   (A=x, B=Bex =Wt,     +bias bt)
//       z=2: C=g_xg    (A=x, B=Bex3=Wg1,    +bias g_bgog)
// ---------------------------------------------------------------------
#define GASTG 18432
#define GBSTG 16896
#define GSTG  (GASTG + GBSTG)
#define GSMEM (3*GSTG)

__global__ void __launch_bounds__(256, 2)
k_gemm2(int op, const float* __restrict__ Aex, const float* __restrict__ Bex,
        const float* __restrict__ Bex2, const float* __restrict__ Bex3,
        const float* bias, int t0) {
    const float *Ap, *Bp;
    float* Cp;
    const float* xgp = 0;
    int n0 = blockIdx.x * 128;
    const int m0 = blockIdx.y * 128;
    if (op == 2) {
        Ap = g_act;
        if (n0 < 1024) { Bp = Bex;   Cp = g_ttt; }
        else           { Bp = g_Wog; Cp = g_gate; n0 -= 1024; xgp = g_xg; }
    } else if (op == 4) {
        Ap = Aex; Bp = Bex; Cp = g_Wog; bias = 0;
    } else {   // op 7
        Ap = Aex;
        const int z = blockIdx.z;
        if (z == 0)      { Bp = Bex2; Cp = g_base0; bias = 0; }
        else if (z == 1) { Bp = Bex;  Cp = g_tgt; }
        else             { Bp = Bex3; Cp = g_xg; bias = g_bgog; }
    }

    extern __shared__ __align__(16) char smg[];
    const uint32_t smb = (uint32_t)__cvta_generic_to_shared(smg);
    const int tid = threadIdx.x;
    const int tx = tid & 15, ty = tid >> 4;

    unsigned long long acc2[8][4];
    #pragma unroll
    for (int i = 0; i < 8; ++i)
        #pragma unroll
        for (int j = 0; j < 4; ++j) acc2[i][j] = 0ULL;

    uint32_t adst[4], bdst[4];
    const float *asrc[4], *bsrc[4];
    #pragma unroll
    for (int j = 0; j < 4; ++j) {
        int ac = tid + j*256;
        int ar = ac >> 3, aq = ac & 7;
        adst[j] = (uint32_t)(ar*144 + aq*16);
        asrc[j] = Ap + (size_t)(m0 + ar)*1024 + aq*4;
        int bc = tid + j*256;
        int br = bc >> 5, bq = bc & 31;
        bdst[j] = (uint32_t)(GASTG + br*528 + bq*16);
        bsrc[j] = Bp + (size_t)br*1024 + n0 + bq*4;
    }

    {   // prologue: slabs 0,1
        #pragma unroll
        for (int j = 0; j < 4; ++j) cpa16(smb + adst[j], asrc[j]);
        #pragma unroll
        for (int j = 0; j < 4; ++j) cpa16(smb + bdst[j], bsrc[j]);
        asm volatile("cp.async.commit_group;");
        const uint32_t s1 = smb + GSTG;
        #pragma unroll
        for (int j = 0; j < 4; ++j) cpa16(s1 + adst[j], asrc[j] + 32);
        #pragma unroll
        for (int j = 0; j < 4; ++j) cpa16(s1 + bdst[j], bsrc[j] + (size_t)32*1024);
        asm volatile("cp.async.commit_group;");
    }

    int stage = 0;
    for (int it = 0; it < 32; ++it) {
        asm volatile("cp.async.wait_group 1;");
        __syncthreads();
        if (it + 2 < 32) {
            const int k0 = (it + 2) * 32;
            const int ns = (stage + 2 >= 3) ? stage - 1 : stage + 2;
            const uint32_t s = smb + ns * GSTG;
            #pragma unroll
            for (int j = 0; j < 4; ++j) cpa16(s + adst[j], asrc[j] + k0);
            #pragma unroll
            for (int j = 0; j < 4; ++j) cpa16(s + bdst[j], bsrc[j] + (size_t)k0*1024);
            asm volatile("cp.async.commit_group;");
        } else {
            asm volatile("cp.async.commit_group;");
        }
        const uint32_t sA = smb + stage * GSTG;
        const uint32_t sB = sA + GASTG;
        #pragma unroll
        for (int k2 = 0; k2 < 32; k2 += 2) {
            float a0[8], a1[8];
            #pragma unroll
            for (int i = 0; i < 8; ++i) {
                float vx, vy;
                asm("ld.shared.v2.f32 {%0,%1},[%2];" : "=f"(vx), "=f"(vy)
                    : "r"(sA + (uint32_t)((ty*8 + i)*144 + k2*4)));
                a0[i] = vx; a1[i] = vy;
            }
            // B loaded directly as 64-bit lane pairs: no packing movs
            unsigned long long bb0, bb1, bb2, bb3, cb0, cb1, cb2, cb3;
            asm("ld.shared.v2.u64 {%0,%1},[%2];" : "=l"(bb0), "=l"(bb1)
                : "r"(sB + (uint32_t)(k2*528 + tx*16)));
            asm("ld.shared.v2.u64 {%0,%1},[%2];" : "=l"(bb2), "=l"(bb3)
                : "r"(sB + (uint32_t)(k2*528 + 256 + tx*16)));
            asm("ld.shared.v2.u64 {%0,%1},[%2];" : "=l"(cb0), "=l"(cb1)
                : "r"(sB + (uint32_t)((k2+1)*528 + tx*16)));
            asm("ld.shared.v2.u64 {%0,%1},[%2];" : "=l"(cb2), "=l"(cb3)
                : "r"(sB + (uint32_t)((k2+1)*528 + 256 + tx*16)));
            #pragma unroll
            for (int i = 0; i < 8; ++i) {
                unsigned long long a2 = pk2(a0[i], a0[i]);
                ffma2(acc2[i][0], a2, bb0);
                ffma2(acc2[i][1], a2, bb1);
                ffma2(acc2[i][2], a2, bb2);
                ffma2(acc2[i][3], a2, bb3);
                unsigned long long a3 = pk2(a1[i], a1[i]);
                ffma2(acc2[i][0], a3, cb0);
                ffma2(acc2[i][1], a3, cb1);
                ffma2(acc2[i][2], a3, cb2);
                ffma2(acc2[i][3], a3, cb3);
            }
        }
        stage = (stage + 1 >= 3) ? 0 : stage + 1;
    }

    const int cc0 = n0 + tx*4;
    #pragma unroll
    for (int i = 0; i < 8; ++i) {
        const int r = m0 + ty*8 + i;
        float v[8];
        upk2(v[0], v[1], acc2[i][0]);
        upk2(v[2], v[3], acc2[i][1]);
        upk2(v[4], v[5], acc2[i][2]);
        upk2(v[6], v[7], acc2[i][3]);
        if (xgp) {
            const size_t gr = ((size_t)(r >> 6)*SS + t0 + (r & 63))*1024;
            float4 x0 = *(const float4*)&xgp[gr + cc0];
            float4 x1 = *(const float4*)&xgp[gr + cc0 + 64];
            v[0]+=x0.x; v[1]+=x0.y; v[2]+=x0.z; v[3]+=x0.w;
            v[4]+=x1.x; v[5]+=x1.y; v[6]+=x1.z; v[7]+=x1.w;
        } else if (bias) {
            float4 b0 = *(const float4*)&bias[cc0];
            float4 b1 = *(const float4*)&bias[cc0 + 64];
            v[0]+=b0.x; v[1]+=b0.y; v[2]+=b0.z; v[3]+=b0.w;
            v[4]+=b1.x; v[5]+=b1.y; v[6]+=b1.z; v[7]+=b1.w;
        }
        float* d = &Cp[(size_t)r*1024 + cc0];
        *(float4*)(d)      = make_float4(v[0],v[1],v[2],v[3]);
        *(float4*)(d + 64) = make_float4(v[4],v[5],v[6],v[7]);
    }
}

// ---------------------------------------------------------------------
// Gram blocks for current chunk: Gx[b][p] = Xc @ Xp^T. grid (c+1, B).
// ---------------------------------------------------------------------
__global__ void k_xxt(const float* __restrict__ x, int t0) {
    const int p = blockIdx.x, b = blockIdx.y, tid = threadIdx.x;
    const int tq = tid >> 4, tr = tid & 15;
    __shared__ float As[64][33];
    __shared__ float Bs[64][33];
    float acc[4][4];
    #pragma unroll
    for (int i = 0; i < 4; ++i)
        #pragma unroll
        for (int j = 0; j < 4; ++j) acc[i][j] = 0.f;
    for (int h0 = 0; h0 < HH; h0 += 32) {
        int r = tid >> 2, cq = (tid & 3) * 8;
        const float* xa = &x[((size_t)b*SS + t0 + r)*HH + h0 + cq];
        const float* xb = &x[((size_t)b*SS + p*CC + r)*HH + h0 + cq];
        float4 a0 = *(const float4*)xa, a1 = *(const float4*)(xa + 4);
        float4 b0 = *(const float4*)xb, b1 = *(const float4*)(xb + 4);
        As[r][cq+0]=a0.x; As[r][cq+1]=a0.y; As[r][cq+2]=a0.z; As[r][cq+3]=a0.w;
        As[r][cq+4]=a1.x; As[r][cq+5]=a1.y; As[r][cq+6]=a1.z; As[r][cq+7]=a1.w;
        Bs[r][cq+0]=b0.x; Bs[r][cq+1]=b0.y; Bs[r][cq+2]=b0.z; Bs[r][cq+3]=b0.w;
        Bs[r][cq+4]=b1.x; Bs[r][cq+5]=b1.y; Bs[r][cq+6]=b1.z; Bs[r][cq+7]=b1.w;
        __syncthreads();
        #pragma unroll 8
        for (int h = 0; h < 32; ++h) {
            float a0v=As[tq*4+0][h], a1v=As[tq*4+1][h];
            float a2v=As[tq*4+2][h], a3v=As[tq*4+3][h];
            float b0v=Bs[tr*4+0][h], b1v=Bs[tr*4+1][h];
            float b2v=Bs[tr*4+2][h], b3v=Bs[tr*4+3][h];
            acc[0][0]+=a0v*b0v; acc[0][1]+=a0v*b1v; acc[0][2]+=a0v*b2v; acc[0][3]+=a0v*b3v;
            acc[1][0]+=a1v*b0v; acc[1][1]+=a1v*b1v; acc[1][2]+=a1v*b2v; acc[1][3]+=a1v*b3v;
            acc[2][0]+=a2v*b0v; acc[2][1]+=a2v*b1v; acc[2][2]+=a2v*b2v; acc[2][3]+=a2v*b3v;
            acc[3][0]+=a3v*b0v; acc[3][1]+=a3v*b1v; acc[3][2]+=a3v*b2v; acc[3][3]+=a3v*b3v;
        }
        __syncthreads();
    }
    float* g = &g_Gx[(((size_t)b*NCH + p)*CC)*CC];
    #pragma unroll
    for (int i = 0; i < 4; ++i)
        #pragma unroll
        for (int j = 0; j < 4; ++j)
            g[(tq*4+i)*CC + tr*4+j] = acc[i][j];
}

// ---------------------------------------------------------------------
// Cross-chunk correction (c >= 1): g_base = base0 - LRI * sum_{p<c} Gx[p]@Ep
// grid (8, B), 256 thr.
// ---------------------------------------------------------------------
#define XSMEM 49152   // Gs 16KB + Es 32KB

__global__ void __launch_bounds__(256)
k_cross(int c, int t0) {
    extern __shared__ float xsm[];
    float* Gsm = xsm;          // [64 t][64 s]
    float* Esm = xsm + 4096;   // [64 s][128 i]
    const int b = blockIdx.y, ib = blockIdx.x * 128;
    const int tid = threadIdx.x, lane = tid & 31, wq = tid >> 5;

    unsigned long long acc2[8][2];
    #pragma unroll
    for (int r = 0; r < 8; ++r) { acc2[r][0] = 0ULL; acc2[r][1] = 0ULL; }

    for (int p = 0; p < c; ++p) {
        __syncthreads();
        const float4* gsrc = (const float4*)&g_Gx[(((size_t)b*NCH + p)*CC)*CC];
        #pragma unroll
        for (int l = 0; l < 4; ++l)
            ((float4*)Gsm)[tid + l*256] = gsrc[tid + l*256];
        #pragma unroll
        for (int l = 0; l < 8; ++l) {
            int f4 = tid + l*256;
            int s = f4 >> 5, q = f4 & 31;
            ((float4*)Esm)[s*32 + q] =
                *(const float4*)&g_errAll[((size_t)b*SS + p*CC + s)*II + ib + q*4];
        }
        __syncthreads();
        #pragma unroll 4
        for (int s = 0; s < 64; ++s) {
            float4 ev = ((float4*)Esm)[s*32 + lane];
            unsigned long long e0 = pk2(ev.x, ev.y), e1 = pk2(ev.z, ev.w);
            #pragma unroll
            for (int r = 0; r < 8; ++r) {
                float g = Gsm[(wq*8 + r)*64 + s];
                unsigned long long g2 = pk2(g, g);
                ffma2(acc2[r][0], g2, e0);
                ffma2(acc2[r][1], g2, e1);
            }
        }
    }
    #pragma unroll
    for (int r = 0; r < 8; ++r) {
        const int t = wq*8 + r;
        float v0, v1, v2, v3;
        upk2(v0, v1, acc2[r][0]);
        upk2(v2, v3, acc2[r][1]);
        float4 bb = *(const float4*)&g_base0[((size_t)b*SS + t0 + t)*II + ib + lane*4];
        *(float4*)&g_base[((b<<6) + t)*II + ib + lane*4] =
            make_float4(bb.x - LRI*v0, bb.y - LRI*v1, bb.z - LRI*v2, bb.w - LRI*v3);
    }
}

// ---------------------------------------------------------------------
// Intra-chunk recurrence. c==0 reads g_base0 directly (no k_cross copy).
// ---------------------------------------------------------------------
__global__ void k_recur(int c, int t0) {
    __shared__ float Gs[CC*CC];
    const int b = blockIdx.y;
    const int i = blockIdx.x * 256 + threadIdx.x;
    const int tid = threadIdx.x;
    const float* gsrc = &g_Gx[(((size_t)b*NCH + c)*CC)*CC];
    #pragma unroll
    for (int l = 0; l < 16; ++l)
        Gs[tid + l*256] = LRI * (gsrc[tid + l*256] + 1.0f);
    __syncthreads();

    const float* bsrc;
    if (c == 0) bsrc = &g_base0[((size_t)b*SS + t0)*II + i];
    else        bsrc = &g_base[((size_t)(b<<6))*II + i];

    float bstv = g_bst[b*II + i];
    float eh[CC];
    float sumerr = 0.f;
    #pragma unroll
    for (int t = 0; t < CC; ++t) {
        float inner = bsrc[(size_t)t*II] + bstv;
        #pragma unroll
        for (int s = 0; s < t; ++s) inner -= Gs[t*CC + s] * eh[s];
        float tg = g_tgt[((size_t)b*SS + t0 + t)*II + i];
        float e = inner - tg;
        eh[t] = e; sumerr += e;
        g_errAll[((size_t)b*SS + t0 + t)*II + i] = e;
        g_act[((b<<6)+t)*II + i] = inner / (1.0f + expf(-inner));
    }
    g_bst[b*II + i] = bstv - LRI * sumerr;
}

// ---------------------------------------------------------------------
__global__ void k_epi(const float* __restrict__ x, const float* __restrict__ gamma,
                      const float* __restrict__ beta, float* __restrict__ out, int t0) {
    const int row = blockIdx.x;
    const int b = row >> 6, t = row & 63;
    const int tid = threadIdx.x;
    const size_t xr = ((size_t)b*SS + t0 + t)*HH;
    float z[4], lsum = 0.f, lsq = 0.f;
    #pragma unroll
    for (int l = 0; l < 4; ++l) {
        int j = tid + l*256;
        float tv = g_ttt[(size_t)row*HH + j];
        float gv = g_gate[(size_t)row*HH + j];
        float gate = 1.0f / (1.0f + expf(-gv));
        float xv = x[xr + j];
        float zz = gate*tv + (1.0f - gate)*xv;
        z[l] = zz; lsum += zz; lsq += zz*zz;
    }
    __shared__ float s1[8], s2[8];
    #pragma unroll
    for (int off = 16; off > 0; off >>= 1) {
        lsum += __shfl_xor_sync(0xFFFFFFFFu, lsum, off);
        lsq  += __shfl_xor_sync(0xFFFFFFFFu, lsq,  off);
    }
    int lane = tid & 31, wid = tid >> 5;
    if (lane == 0) { s1[wid] = lsum; s2[wid] = lsq; }
    __syncthreads();
    if (wid == 0) {
        float v1 = (lane < 8) ? s1[lane] : 0.f;
        float v2 = (lane < 8) ? s2[lane] : 0.f;
        #pragma unroll
        for (int off = 4; off > 0; off >>= 1) {
            v1 += __shfl_xor_sync(0xFFFFFFFFu, v1, off);
            v2 += __shfl_xor_sync(0xFFFFFFFFu, v2, off);
        }
        if (lane == 0) { s1[0] = v1; s2[0] = v2; }
    }
    __syncthreads();
    float mu  = s1[0] * (1.0f / HH);
    float var = s2[0] * (1.0f / HH) - mu*mu;
    float inv = rsqrtf(var + EPSF);
    #pragma unroll
    for (int l = 0; l < 4; ++l) {
        int j = tid + l*256;
        out[xr + j] = (z[l] - mu) * inv * gamma[j] + beta[j];
    }
}

// ---------------------------------------------------------------------
extern "C" void kernel_launch(void* const* d_in, const int* in_sizes, int n_in,
                              void* d_out, int out_size) {
    const float* x      = (const float*)d_in[0];
    const float* W_init = (const float*)d_in[1];
    const float* b_init = (const float*)d_in[2];
    const float* Wt     = (const float*)d_in[3];
    const float* bt     = (const float*)d_in[4];
    const float* Wo     = (const float*)d_in[5];
    const float* bo     = (const float*)d_in[6];
    const float* Wg     = (const float*)d_in[7];
    const float* bg     = (const float*)d_in[8];
    const float* gamma  = (const float*)d_in[9];
    const float* beta   = (const float*)d_in[10];
    float* out = (float*)d_out;

    static int attr_done = 0;
    if (!attr_done) {
        cudaFuncSetAttribute(k_gemm2, cudaFuncAttributeMaxDynamicSharedMemorySize, GSMEM);
        cudaFuncSetAttribute(k_cross, cudaFuncAttributeMaxDynamicSharedMemorySize, XSMEM);
        attr_done = 1;
    }

    k_initb<<<64, 1024>>>(b_init);                                       // 0
    k_bgog<<<4, 256>>>(bo, bg, Wg + 1024*1024);                          // 1
    k_gemm2<<<dim3(8,8), 256, GSMEM>>>(4, Wo, Wg + 1024*1024, 0, 0, 0, 0); // 2: Wog
    // merged big GEMMs: z=0 base0 (W_init), z=1 tgt (Wt,+bt), z=2 xg (Wg1,+bgog)
    k_gemm2<<<dim3(8,256,3), 256, GSMEM>>>(7, x, Wt, W_init, Wg, bt, 0); // 3
    k_xxt<<<dim3(1, BB), 256>>>(x, 0);                                   // 4
    k_recur<<<dim3(4, BB), 256>>>(0, 0);                                 // 5
    k_gemm2<<<dim3(16,32), 256, GSMEM>>>(2, 0, Wo, 0, 0, bo, 0);         // 6
    k_epi<<<BB*CC, 256>>>(x, gamma, beta, out, 0);                       // 7

    for (int c = 1; c < NCH; ++c) {
        const int t0 = c * CC;
        k_xxt<<<dim3(c + 1, BB), 256>>>(x, t0);
        k_cross<<<dim3(8, BB), 256, XSMEM>>>(c, t0);
        k_recur<<<dim3(4, BB), 256>>>(c, t0);
        k_gemm2<<<dim3(16,32), 256, GSMEM>>>(2, 0, Wo, 0, 0, bo, t0);
        k_epi<<<BB*CC, 256>>>(x, gamma, beta, out, t0);
    }
}

// round 17
// speedup vs baseline: 1.6425x; 1.0477x over previous
#include <cuda_runtime.h>
#include <stdint.h>
#include <math.h>

#define BB 64
#define SS 512
#define HH 1024
#define II 1024
#define CC 64
#define NCH (SS/CC)
#define LRI (0.01f/1024.0f)
#define EPSF 1e-5f

// ---------------- device state (no allocation allowed) ----------------
__device__ float g_bst[BB*II];
__device__ float g_tgt[(size_t)BB*SS*II];     // x@Wt + bt
__device__ float g_xg[(size_t)BB*SS*HH];      // x@Wg1 + bg + bo@Wg2
__device__ float g_base0[(size_t)BB*SS*II];   // x@W_init
__device__ float g_errAll[(size_t)BB*SS*II];  // full err history
__device__ float g_base[BB*CC*II];            // base0 - LRI*cross (chunks c>0)
__device__ float g_act[2*(size_t)BB*CC*II];   // silu(inner), double-buffered
__device__ float g_ttt[BB*CC*HH];
__device__ float g_gate[BB*CC*HH];
__device__ float g_Gx[(size_t)BB*NCH*CC*CC];  // Gram row for current chunk
__device__ float g_Wog[HH*HH];                // Wo @ Wg2
__device__ float g_bgog[HH];                  // bg + bo@Wg2

// ------------------------- helpers -------------------------
__device__ __forceinline__ void cpa16(uint32_t s, const void* g) {
    asm volatile("cp.async.cg.shared.global [%0], [%1], 16;" :: "r"(s), "l"(g));
}
__device__ __forceinline__ void ffma2(unsigned long long& c, unsigned long long a,
                                      unsigned long long b) {
    asm("fma.rn.f32x2 %0, %1, %2, %0;" : "+l"(c) : "l"(a), "l"(b));
}
__device__ __forceinline__ unsigned long long pk2(float lo, float hi) {
    unsigned long long r;
    asm("mov.b64 %0, {%1, %2};" : "=l"(r) : "f"(lo), "f"(hi));
    return r;
}
__device__ __forceinline__ void upk2(float& lo, float& hi, unsigned long long v) {
    asm("mov.b64 {%0, %1}, %2;" : "=f"(lo), "=f"(hi) : "l"(v));
}

// ---------------------------------------------------------------------
__global__ void k_initb(const float* __restrict__ bi) {
    int i = blockIdx.x * 1024 + threadIdx.x;
    g_bst[i] = bi[i & 1023];
}

__global__ void k_bgog(const float* __restrict__ bo, const float* __restrict__ bg,
                       const float* __restrict__ Wg2) {
    int n = blockIdx.x * 256 + threadIdx.x;
    float s = bg[n];
    for (int j = 0; j < 1024; ++j) s += bo[j] * Wg2[(size_t)j*1024 + n];
    g_bgog[n] = s;
}

// ---------------------------------------------------------------------
// FFMA2 fp32 GEMM: 128x128 tile, 256 thr, K-slab 32, 3-stage cp.async.
// op 2: chunk fused, grid(16,32): nb<8 -> g_ttt (B=Bex=Wo, +bias bo);
//       nb>=8 -> g_gate (B=g_Wog, +xg row for t0). A = g_act[par].
// op 4: C=g_Wog (A=Aex=Wo, B=Bex=Wg2, no bias)
// op 7: merged big GEMMs, grid (8,256,3):
//       z=0: g_base0 (B=Bex2=W_init), z=1: g_tgt (B=Bex=Wt,+bt),
//       z=2: g_xg (B=Bex3=Wg1, +g_bgog)
// ---------------------------------------------------------------------
#define GASTG 18432
#define GBSTG 16896
#define GSTG  (GASTG + GBSTG)
#define GSMEM (3*GSTG)

__global__ void __launch_bounds__(256, 2)
k_gemm2(int op, const float* __restrict__ Aex, const float* __restrict__ Bex,
        const float* __restrict__ Bex2, const float* __restrict__ Bex3,
        const float* bias, int t0, int par) {
    const float *Ap, *Bp;
    float* Cp;
    const float* xgp = 0;
    int n0 = blockIdx.x * 128;
    const int m0 = blockIdx.y * 128;
    if (op == 2) {
        Ap = g_act + (size_t)par*BB*CC*II;
        if (n0 < 1024) { Bp = Bex;   Cp = g_ttt; }
        else           { Bp = g_Wog; Cp = g_gate; n0 -= 1024; xgp = g_xg; }
    } else if (op == 4) {
        Ap = Aex; Bp = Bex; Cp = g_Wog; bias = 0;
    } else {   // op 7
        Ap = Aex;
        const int z = blockIdx.z;
        if (z == 0)      { Bp = Bex2; Cp = g_base0; bias = 0; }
        else if (z == 1) { Bp = Bex;  Cp = g_tgt; }
        else             { Bp = Bex3; Cp = g_xg; bias = g_bgog; }
    }

    extern __shared__ __align__(16) char smg[];
    const uint32_t smb = (uint32_t)__cvta_generic_to_shared(smg);
    const int tid = threadIdx.x;
    const int tx = tid & 15, ty = tid >> 4;

    unsigned long long acc2[8][4];
    #pragma unroll
    for (int i = 0; i < 8; ++i)
        #pragma unroll
        for (int j = 0; j < 4; ++j) acc2[i][j] = 0ULL;

    uint32_t adst[4], bdst[4];
    const float *asrc[4], *bsrc[4];
    #pragma unroll
    for (int j = 0; j < 4; ++j) {
        int ac = tid + j*256;
        int ar = ac >> 3, aq = ac & 7;
        adst[j] = (uint32_t)(ar*144 + aq*16);
        asrc[j] = Ap + (size_t)(m0 + ar)*1024 + aq*4;
        int bc = tid + j*256;
        int br = bc >> 5, bq = bc & 31;
        bdst[j] = (uint32_t)(GASTG + br*528 + bq*16);
        bsrc[j] = Bp + (size_t)br*1024 + n0 + bq*4;
    }

    {   // prologue: slabs 0,1
        #pragma unroll
        for (int j = 0; j < 4; ++j) cpa16(smb + adst[j], asrc[j]);
        #pragma unroll
        for (int j = 0; j < 4; ++j) cpa16(smb + bdst[j], bsrc[j]);
        asm volatile("cp.async.commit_group;");
        const uint32_t s1 = smb + GSTG;
        #pragma unroll
        for (int j = 0; j < 4; ++j) cpa16(s1 + adst[j], asrc[j] + 32);
        #pragma unroll
        for (int j = 0; j < 4; ++j) cpa16(s1 + bdst[j], bsrc[j] + (size_t)32*1024);
        asm volatile("cp.async.commit_group;");
    }

    int stage = 0;
    for (int it = 0; it < 32; ++it) {
        asm volatile("cp.async.wait_group 1;");
        __syncthreads();
        if (it + 2 < 32) {
            const int k0 = (it + 2) * 32;
            const int ns = (stage + 2 >= 3) ? stage - 1 : stage + 2;
            const uint32_t s = smb + ns * GSTG;
            #pragma unroll
            for (int j = 0; j < 4; ++j) cpa16(s + adst[j], asrc[j] + k0);
            #pragma unroll
            for (int j = 0; j < 4; ++j) cpa16(s + bdst[j], bsrc[j] + (size_t)k0*1024);
            asm volatile("cp.async.commit_group;");
        } else {
            asm volatile("cp.async.commit_group;");
        }
        const uint32_t sA = smb + stage * GSTG;
        const uint32_t sB = sA + GASTG;
        #pragma unroll
        for (int k2 = 0; k2 < 32; k2 += 2) {
            float a0[8], a1[8];
            #pragma unroll
            for (int i = 0; i < 8; ++i) {
                float vx, vy;
                asm("ld.shared.v2.f32 {%0,%1},[%2];" : "=f"(vx), "=f"(vy)
                    : "r"(sA + (uint32_t)((ty*8 + i)*144 + k2*4)));
                a0[i] = vx; a1[i] = vy;
            }
            unsigned long long bb0, bb1, bb2, bb3, cb0, cb1, cb2, cb3;
            asm("ld.shared.v2.u64 {%0,%1},[%2];" : "=l"(bb0), "=l"(bb1)
                : "r"(sB + (uint32_t)(k2*528 + tx*16)));
            asm("ld.shared.v2.u64 {%0,%1},[%2];" : "=l"(bb2), "=l"(bb3)
                : "r"(sB + (uint32_t)(k2*528 + 256 + tx*16)));
            asm("ld.shared.v2.u64 {%0,%1},[%2];" : "=l"(cb0), "=l"(cb1)
                : "r"(sB + (uint32_t)((k2+1)*528 + tx*16)));
            asm("ld.shared.v2.u64 {%0,%1},[%2];" : "=l"(cb2), "=l"(cb3)
                : "r"(sB + (uint32_t)((k2+1)*528 + 256 + tx*16)));
            #pragma unroll
            for (int i = 0; i < 8; ++i) {
                unsigned long long a2 = pk2(a0[i], a0[i]);
                ffma2(acc2[i][0], a2, bb0);
                ffma2(acc2[i][1], a2, bb1);
                ffma2(acc2[i][2], a2, bb2);
                ffma2(acc2[i][3], a2, bb3);
                unsigned long long a3 = pk2(a1[i], a1[i]);
                ffma2(acc2[i][0], a3, cb0);
                ffma2(acc2[i][1], a3, cb1);
                ffma2(acc2[i][2], a3, cb2);
                ffma2(acc2[i][3], a3, cb3);
            }
        }
        stage = (stage + 1 >= 3) ? 0 : stage + 1;
    }

    const int cc0 = n0 + tx*4;
    #pragma unroll
    for (int i = 0; i < 8; ++i) {
        const int r = m0 + ty*8 + i;
        float v[8];
        upk2(v[0], v[1], acc2[i][0]);
        upk2(v[2], v[3], acc2[i][1]);
        upk2(v[4], v[5], acc2[i][2]);
        upk2(v[6], v[7], acc2[i][3]);
        if (xgp) {
            const size_t gr = ((size_t)(r >> 6)*SS + t0 + (r & 63))*1024;
            float4 x0 = *(const float4*)&xgp[gr + cc0];
            float4 x1 = *(const float4*)&xgp[gr + cc0 + 64];
            v[0]+=x0.x; v[1]+=x0.y; v[2]+=x0.z; v[3]+=x0.w;
            v[4]+=x1.x; v[5]+=x1.y; v[6]+=x1.z; v[7]+=x1.w;
        } else if (bias) {
            float4 b0 = *(const float4*)&bias[cc0];
            float4 b1 = *(const float4*)&bias[cc0 + 64];
            v[0]+=b0.x; v[1]+=b0.y; v[2]+=b0.z; v[3]+=b0.w;
            v[4]+=b1.x; v[5]+=b1.y; v[6]+=b1.z; v[7]+=b1.w;
        }
        float* d = &Cp[(size_t)r*1024 + cc0];
        *(float4*)(d)      = make_float4(v[0],v[1],v[2],v[3]);
        *(float4*)(d + 64) = make_float4(v[4],v[5],v[6],v[7]);
    }
}

// ---------------------------------------------------------------------
// Gram blocks for current chunk: Gx[b][p] = Xc @ Xp^T. grid (c+1, B).
// ---------------------------------------------------------------------
__global__ void k_xxt(const float* __restrict__ x, int t0) {
    const int p = blockIdx.x, b = blockIdx.y, tid = threadIdx.x;
    const int tq = tid >> 4, tr = tid & 15;
    __shared__ float As[64][33];
    __shared__ float Bs[64][33];
    float acc[4][4];
    #pragma unroll
    for (int i = 0; i < 4; ++i)
        #pragma unroll
        for (int j = 0; j < 4; ++j) acc[i][j] = 0.f;
    for (int h0 = 0; h0 < HH; h0 += 32) {
        int r = tid >> 2, cq = (tid & 3) * 8;
        const float* xa = &x[((size_t)b*SS + t0 + r)*HH + h0 + cq];
        const float* xb = &x[((size_t)b*SS + p*CC + r)*HH + h0 + cq];
        float4 a0 = *(const float4*)xa, a1 = *(const float4*)(xa + 4);
        float4 b0 = *(const float4*)xb, b1 = *(const float4*)(xb + 4);
        As[r][cq+0]=a0.x; As[r][cq+1]=a0.y; As[r][cq+2]=a0.z; As[r][cq+3]=a0.w;
        As[r][cq+4]=a1.x; As[r][cq+5]=a1.y; As[r][cq+6]=a1.z; As[r][cq+7]=a1.w;
        Bs[r][cq+0]=b0.x; Bs[r][cq+1]=b0.y; Bs[r][cq+2]=b0.z; Bs[r][cq+3]=b0.w;
        Bs[r][cq+4]=b1.x; Bs[r][cq+5]=b1.y; Bs[r][cq+6]=b1.z; Bs[r][cq+7]=b1.w;
        __syncthreads();
        #pragma unroll 8
        for (int h = 0; h < 32; ++h) {
            float a0v=As[tq*4+0][h], a1v=As[tq*4+1][h];
            float a2v=As[tq*4+2][h], a3v=As[tq*4+3][h];
            float b0v=Bs[tr*4+0][h], b1v=Bs[tr*4+1][h];
            float b2v=Bs[tr*4+2][h], b3v=Bs[tr*4+3][h];
            acc[0][0]+=a0v*b0v; acc[0][1]+=a0v*b1v; acc[0][2]+=a0v*b2v; acc[0][3]+=a0v*b3v;
            acc[1][0]+=a1v*b0v; acc[1][1]+=a1v*b1v; acc[1][2]+=a1v*b2v; acc[1][3]+=a1v*b3v;
            acc[2][0]+=a2v*b0v; acc[2][1]+=a2v*b1v; acc[2][2]+=a2v*b2v; acc[2][3]+=a2v*b3v;
            acc[3][0]+=a3v*b0v; acc[3][1]+=a3v*b1v; acc[3][2]+=a3v*b2v; acc[3][3]+=a3v*b3v;
        }
        __syncthreads();
    }
    float* g = &g_Gx[(((size_t)b*NCH + p)*CC)*CC];
    #pragma unroll
    for (int i = 0; i < 4; ++i)
        #pragma unroll
        for (int j = 0; j < 4; ++j)
            g[(tq*4+i)*CC + tr*4+j] = acc[i][j];
}

// ---------------------------------------------------------------------
// Cross-chunk correction (c >= 1). grid (8, B), 256 thr.
// ---------------------------------------------------------------------
#define XSMEM 49152

__global__ void __launch_bounds__(256)
k_cross(int c, int t0) {
    extern __shared__ float xsm[];
    float* Gsm = xsm;
    float* Esm = xsm + 4096;
    const int b = blockIdx.y, ib = blockIdx.x * 128;
    const int tid = threadIdx.x, lane = tid & 31, wq = tid >> 5;

    unsigned long long acc2[8][2];
    #pragma unroll
    for (int r = 0; r < 8; ++r) { acc2[r][0] = 0ULL; acc2[r][1] = 0ULL; }

    for (int p = 0; p < c; ++p) {
        __syncthreads();
        const float4* gsrc = (const float4*)&g_Gx[(((size_t)b*NCH + p)*CC)*CC];
        #pragma unroll
        for (int l = 0; l < 4; ++l)
            ((float4*)Gsm)[tid + l*256] = gsrc[tid + l*256];
        #pragma unroll
        for (int l = 0; l < 8; ++l) {
            int f4 = tid + l*256;
            int s = f4 >> 5, q = f4 & 31;
            ((float4*)Esm)[s*32 + q] =
                *(const float4*)&g_errAll[((size_t)b*SS + p*CC + s)*II + ib + q*4];
        }
        __syncthreads();
        #pragma unroll 4
        for (int s = 0; s < 64; ++s) {
            float4 ev = ((float4*)Esm)[s*32 + lane];
            unsigned long long e0 = pk2(ev.x, ev.y), e1 = pk2(ev.z, ev.w);
            #pragma unroll
            for (int r = 0; r < 8; ++r) {
                float g = Gsm[(wq*8 + r)*64 + s];
                unsigned long long g2 = pk2(g, g);
                ffma2(acc2[r][0], g2, e0);
                ffma2(acc2[r][1], g2, e1);
            }
        }
    }
    #pragma unroll
    for (int r = 0; r < 8; ++r) {
        const int t = wq*8 + r;
        float v0, v1, v2, v3;
        upk2(v0, v1, acc2[r][0]);
        upk2(v2, v3, acc2[r][1]);
        float4 bb = *(const float4*)&g_base0[((size_t)b*SS + t0 + t)*II + ib + lane*4];
        *(float4*)&g_base[((b<<6) + t)*II + ib + lane*4] =
            make_float4(bb.x - LRI*v0, bb.y - LRI*v1, bb.z - LRI*v2, bb.w - LRI*v3);
    }
}

// ---------------------------------------------------------------------
// Intra-chunk recurrence. Writes act into buffer 'par'.
// ---------------------------------------------------------------------
__global__ void k_recur(int c, int t0, int par) {
    __shared__ float Gs[CC*CC];
    const int b = blockIdx.y;
    const int i = blockIdx.x * 256 + threadIdx.x;
    const int tid = threadIdx.x;
    const float* gsrc = &g_Gx[(((size_t)b*NCH + c)*CC)*CC];
    #pragma unroll
    for (int l = 0; l < 16; ++l)
        Gs[tid + l*256] = LRI * (gsrc[tid + l*256] + 1.0f);
    __syncthreads();

    const float* bsrc;
    if (c == 0) bsrc = &g_base0[((size_t)b*SS + t0)*II + i];
    else        bsrc = &g_base[((size_t)(b<<6))*II + i];
    float* actp = g_act + (size_t)par*BB*CC*II;

    float bstv = g_bst[b*II + i];
    float eh[CC];
    float sumerr = 0.f;
    #pragma unroll
    for (int t = 0; t < CC; ++t) {
        float inner = bsrc[(size_t)t*II] + bstv;
        #pragma unroll
        for (int s = 0; s < t; ++s) inner -= Gs[t*CC + s] * eh[s];
        float tg = g_tgt[((size_t)b*SS + t0 + t)*II + i];
        float e = inner - tg;
        eh[t] = e; sumerr += e;
        g_errAll[((size_t)b*SS + t0 + t)*II + i] = e;
        actp[((b<<6)+t)*II + i] = inner / (1.0f + expf(-inner));
    }
    g_bst[b*II + i] = bstv - LRI * sumerr;
}

// ---------------------------------------------------------------------
__global__ void k_epi(const float* __restrict__ x, const float* __restrict__ gamma,
                      const float* __restrict__ beta, float* __restrict__ out, int t0) {
    const int row = blockIdx.x;
    const int b = row >> 6, t = row & 63;
    const int tid = threadIdx.x;
    const size_t xr = ((size_t)b*SS + t0 + t)*HH;
    float z[4], lsum = 0.f, lsq = 0.f;
    #pragma unroll
    for (int l = 0; l < 4; ++l) {
        int j = tid + l*256;
        float tv = g_ttt[(size_t)row*HH + j];
        float gv = g_gate[(size_t)row*HH + j];
        float gate = 1.0f / (1.0f + expf(-gv));
        float xv = x[xr + j];
        float zz = gate*tv + (1.0f - gate)*xv;
        z[l] = zz; lsum += zz; lsq += zz*zz;
    }
    __shared__ float s1[8], s2[8];
    #pragma unroll
    for (int off = 16; off > 0; off >>= 1) {
        lsum += __shfl_xor_sync(0xFFFFFFFFu, lsum, off);
        lsq  += __shfl_xor_sync(0xFFFFFFFFu, lsq,  off);
    }
    int lane = tid & 31, wid = tid >> 5;
    if (lane == 0) { s1[wid] = lsum; s2[wid] = lsq; }
    __syncthreads();
    if (wid == 0) {
        float v1 = (lane < 8) ? s1[lane] : 0.f;
        float v2 = (lane < 8) ? s2[lane] : 0.f;
        #pragma unroll
        for (int off = 4; off > 0; off >>= 1) {
            v1 += __shfl_xor_sync(0xFFFFFFFFu, v1, off);
            v2 += __shfl_xor_sync(0xFFFFFFFFu, v2, off);
        }
        if (lane == 0) { s1[0] = v1; s2[0] = v2; }
    }
    __syncthreads();
    float mu  = s1[0] * (1.0f / HH);
    float var = s2[0] * (1.0f / HH) - mu*mu;
    float inv = rsqrtf(var + EPSF);
    #pragma unroll
    for (int l = 0; l < 4; ++l) {
        int j = tid + l*256;
        out[xr + j] = (z[l] - mu) * inv * gamma[j] + beta[j];
    }
}

// ---------------------------------------------------------------------
extern "C" void kernel_launch(void* const* d_in, const int* in_sizes, int n_in,
                              void* d_out, int out_size) {
    const float* x      = (const float*)d_in[0];
    const float* W_init = (const float*)d_in[1];
    const float* b_init = (const float*)d_in[2];
    const float* Wt     = (const float*)d_in[3];
    const float* bt     = (const float*)d_in[4];
    const float* Wo     = (const float*)d_in[5];
    const float* bo     = (const float*)d_in[6];
    const float* Wg     = (const float*)d_in[7];
    const float* bg     = (const float*)d_in[8];
    const float* gamma  = (const float*)d_in[9];
    const float* beta   = (const float*)d_in[10];
    float* out = (float*)d_out;

    static int inited = 0;
    static cudaStream_t sB;
    static cudaEvent_t evA[NCH], evG[NCH], evFin;
    if (!inited) {
        cudaFuncSetAttribute(k_gemm2, cudaFuncAttributeMaxDynamicSharedMemorySize, GSMEM);
        cudaFuncSetAttribute(k_cross, cudaFuncAttributeMaxDynamicSharedMemorySize, XSMEM);
        cudaStreamCreateWithFlags(&sB, cudaStreamNonBlocking);
        for (int i = 0; i < NCH; ++i) {
            cudaEventCreateWithFlags(&evA[i], cudaEventDisableTiming);
            cudaEventCreateWithFlags(&evG[i], cudaEventDisableTiming);
        }
        cudaEventCreateWithFlags(&evFin, cudaEventDisableTiming);
        inited = 1;
    }

    // ---- startup (main stream) ----
    k_initb<<<64, 1024>>>(b_init);
    k_bgog<<<4, 256>>>(bo, bg, Wg + 1024*1024);
    k_gemm2<<<dim3(8,8), 256, GSMEM>>>(4, Wo, Wg + 1024*1024, 0, 0, 0, 0, 0);
    k_gemm2<<<dim3(8,256,3), 256, GSMEM>>>(7, x, Wt, W_init, Wg, bt, 0, 0);

    // ---- chunk pipeline: s0 = xxt/cross/recur, sB = gemm/epi ----
    for (int c = 0; c < NCH; ++c) {
        const int t0 = c * CC;
        const int par = c & 1;
        k_xxt<<<dim3(c + 1, BB), 256>>>(x, t0);
        if (c > 0) k_cross<<<dim3(8, BB), 256, XSMEM>>>(c, t0);
        if (c >= 2) cudaStreamWaitEvent(0, evG[c - 2], 0);   // WAR guard on g_act[par]
        k_recur<<<dim3(4, BB), 256>>>(c, t0, par);
        cudaEventRecord(evA[c], 0);
        cudaStreamWaitEvent(sB, evA[c], 0);
        k_gemm2<<<dim3(16,32), 256, GSMEM, sB>>>(2, 0, Wo, 0, 0, bo, t0, par);
        cudaEventRecord(evG[c], sB);
        k_epi<<<BB*CC, 256, 0, sB>>>(x, gamma, beta, out, t0);
    }
    // join forked stream back before returning (required for graph capture)
    cudaEventRecord(evFin, sB);
    cudaStreamWaitEvent(0, evFin, 0);
}